// round 1
// baseline (speedup 1.0000x reference)
#include <cuda_runtime.h>
#include <math.h>

#define N_NODES  100000
#define N_EDGES  3200000
#define N_GRAPHS 1024
#define F        128

// ---------------- scratch (device globals; no allocation allowed) ----------
__device__ float g_bufA[(size_t)N_NODES * F];
__device__ float g_bufB[(size_t)N_NODES * F];
__device__ float g_agg [(size_t)N_NODES * F];
__device__ int   g_cnt[N_NODES];
__device__ int   g_rowstart[N_NODES + 1];
__device__ int   g_cursor[N_NODES];
__device__ int   g_ssrc[N_EDGES];
__device__ float g_pool[N_GRAPHS * F];

// ---------------- init: zero histogram + pool ------------------------------
__global__ void init_kernel() {
    int i = blockIdx.x * blockDim.x + threadIdx.x;
    if (i < N_NODES) g_cnt[i] = 0;
    if (i < N_GRAPHS * F) g_pool[i] = 0.0f;
}

// ---------------- histogram of dst ------------------------------------------
__global__ void hist_kernel(const int* __restrict__ dst) {
    int i = blockIdx.x * blockDim.x + threadIdx.x;
    if (i < N_EDGES) atomicAdd(&g_cnt[dst[i]], 1);
}

// ---------------- single-block exclusive scan over counts ------------------
__global__ void scan_kernel() {
    __shared__ int wsum[32];
    __shared__ int sh_carry;
    int tid = threadIdx.x, lane = tid & 31, wid = tid >> 5;
    if (tid == 0) sh_carry = 0;
    __syncthreads();
    for (int base = 0; base < N_NODES; base += 1024) {
        int i = base + tid;
        int v = (i < N_NODES) ? g_cnt[i] : 0;
        int val = v;
#pragma unroll
        for (int off = 1; off < 32; off <<= 1) {
            int n = __shfl_up_sync(0xffffffffu, val, off);
            if (lane >= off) val += n;
        }
        if (lane == 31) wsum[wid] = val;
        __syncthreads();
        if (wid == 0) {
            int w = wsum[lane];
            int wv = w;
#pragma unroll
            for (int off = 1; off < 32; off <<= 1) {
                int n = __shfl_up_sync(0xffffffffu, wv, off);
                if (lane >= off) wv += n;
            }
            wsum[lane] = wv - w;  // exclusive warp offset
        }
        __syncthreads();
        int excl = sh_carry + wsum[wid] + val - v;
        if (i < N_NODES) { g_rowstart[i] = excl; g_cursor[i] = excl; }
        __syncthreads();
        if (tid == 1023) sh_carry = excl + v;   // running total
        __syncthreads();
    }
    if (threadIdx.x == 0) g_rowstart[N_NODES] = sh_carry;
}

// ---------------- scatter edges into CSR-by-dst -----------------------------
__global__ void scatter_kernel(const int* __restrict__ src, const int* __restrict__ dst) {
    int i = blockIdx.x * blockDim.x + threadIdx.x;
    if (i < N_EDGES) {
        int p = atomicAdd(&g_cursor[dst[i]], 1);
        g_ssrc[p] = src[i];
    }
}

// ---------------- aggregation: warp per node, atomic-free ------------------
__global__ void agg_kernel(const float* __restrict__ xin) {
    int warp = (blockIdx.x * blockDim.x + threadIdx.x) >> 5;
    int lane = threadIdx.x & 31;
    if (warp >= N_NODES) return;
    int beg = g_rowstart[warp];
    int end = g_rowstart[warp + 1];
    const float4* xv = (const float4*)xin;
    float4 acc = make_float4(0.f, 0.f, 0.f, 0.f);
    for (int e = beg; e < end; e++) {
        int s = __ldg(&g_ssrc[e]);
        float4 v = __ldg(&xv[(size_t)s * 32 + lane]);
        acc.x += v.x; acc.y += v.y; acc.z += v.z; acc.w += v.w;
    }
    ((float4*)g_agg)[(size_t)warp * 32 + lane] = acc;
}

// ---------------- GEMM: out = relu(g_agg @ W + b), [M,128]x[128,128] --------
__global__ __launch_bounds__(256, 1)
void gemm_bias_relu(const float* __restrict__ W, const float* __restrict__ bias,
                    float* __restrict__ out, int M) {
    extern __shared__ float sm[];
    float* As = sm;            // [k][row]  128x128 (k-major, transposed)
    float* Ws = sm + 128 * 128;  // [k][col]  128x128
    int tid = threadIdx.x;
    long row0 = (long)blockIdx.x * 128;

    // load W (already [k][col] row-major)
    const float4* Wv = (const float4*)W;
    float4* Wsv = (float4*)Ws;
#pragma unroll
    for (int i = tid; i < 4096; i += 256) Wsv[i] = Wv[i];

    // load A tile transposed: thread handles (kq, row) so STS is conflict-free
    const float4* Av = (const float4*)g_agg;
    for (int i = tid; i < 4096; i += 256) {
        int kq = i >> 7;        // 0..31
        int r  = i & 127;       // 0..127
        float4 v;
        if (row0 + r < M) v = __ldg(&Av[(row0 + r) * 32 + kq]);
        else              v = make_float4(0.f, 0.f, 0.f, 0.f);
        int k = kq * 4;
        As[(k + 0) * 128 + r] = v.x;
        As[(k + 1) * 128 + r] = v.y;
        As[(k + 2) * 128 + r] = v.z;
        As[(k + 3) * 128 + r] = v.w;
    }
    __syncthreads();

    int tr = (tid >> 4) * 8;   // row offset of 8-row micro tile
    int tc = (tid & 15) * 8;   // col offset of 8-col micro tile
    float acc[8][8];
#pragma unroll
    for (int i = 0; i < 8; i++)
#pragma unroll
        for (int j = 0; j < 8; j++) acc[i][j] = 0.f;

#pragma unroll 4
    for (int k = 0; k < 128; k++) {
        float4 a0 = *(const float4*)&As[k * 128 + tr];
        float4 a1 = *(const float4*)&As[k * 128 + tr + 4];
        float4 b0 = *(const float4*)&Ws[k * 128 + tc];
        float4 b1 = *(const float4*)&Ws[k * 128 + tc + 4];
        float a[8] = {a0.x, a0.y, a0.z, a0.w, a1.x, a1.y, a1.z, a1.w};
        float b[8] = {b0.x, b0.y, b0.z, b0.w, b1.x, b1.y, b1.z, b1.w};
#pragma unroll
        for (int i = 0; i < 8; i++)
#pragma unroll
            for (int j = 0; j < 8; j++)
                acc[i][j] = fmaf(a[i], b[j], acc[i][j]);
    }

    // epilogue: bias + relu
    float bb[8];
#pragma unroll
    for (int j = 0; j < 8; j++) bb[j] = __ldg(&bias[tc + j]);
#pragma unroll
    for (int i = 0; i < 8; i++) {
        long r = row0 + tr + i;
        if (r < M) {
            float4 o0, o1;
            o0.x = fmaxf(acc[i][0] + bb[0], 0.f);
            o0.y = fmaxf(acc[i][1] + bb[1], 0.f);
            o0.z = fmaxf(acc[i][2] + bb[2], 0.f);
            o0.w = fmaxf(acc[i][3] + bb[3], 0.f);
            o1.x = fmaxf(acc[i][4] + bb[4], 0.f);
            o1.y = fmaxf(acc[i][5] + bb[5], 0.f);
            o1.z = fmaxf(acc[i][6] + bb[6], 0.f);
            o1.w = fmaxf(acc[i][7] + bb[7], 0.f);
            *(float4*)&out[r * 128 + tc]     = o0;
            *(float4*)&out[r * 128 + tc + 4] = o1;
        }
    }
}

// ---------------- global sum pool (atomic) ----------------------------------
__global__ void pool_kernel(const float* __restrict__ x, const int* __restrict__ batching) {
    int idx = blockIdx.x * blockDim.x + threadIdx.x;   // over N_NODES*32 quads
    if (idx >= N_NODES * 32) return;
    int n = idx >> 5;
    int q = idx & 31;
    int b = __ldg(&batching[n]);
    float4 v = __ldg(&((const float4*)x)[(size_t)n * 32 + q]);
    float* dstp = &g_pool[b * F + q * 4];
    atomicAdd(dstp + 0, v.x);
    atomicAdd(dstp + 1, v.y);
    atomicAdd(dstp + 2, v.z);
    atomicAdd(dstp + 3, v.w);
}

// ---------------- head: FC1 -> FC2 -> softmax --------------------------------
__global__ void head_kernel(const float* __restrict__ Wf1, const float* __restrict__ bf1,
                            const float* __restrict__ Wf2, const float* __restrict__ bf2,
                            float* __restrict__ out) {
    __shared__ float gs[128];
    __shared__ float hs[64];
    __shared__ float logits[10];
    int g = blockIdx.x, tid = threadIdx.x;
    gs[tid] = g_pool[g * F + tid];
    __syncthreads();
    if (tid < 64) {
        float s = __ldg(&bf1[tid]);
#pragma unroll 8
        for (int k = 0; k < 128; k++)
            s = fmaf(gs[k], __ldg(&Wf1[k * 64 + tid]), s);
        hs[tid] = s;
    }
    __syncthreads();
    if (tid < 10) {
        float s = __ldg(&bf2[tid]);
#pragma unroll 8
        for (int k = 0; k < 64; k++)
            s = fmaf(hs[k], __ldg(&Wf2[k * 10 + tid]), s);
        logits[tid] = s;
    }
    __syncthreads();
    if (tid == 0) {
        float m = logits[0];
#pragma unroll
        for (int i = 1; i < 10; i++) m = fmaxf(m, logits[i]);
        float e[10], sum = 0.f;
#pragma unroll
        for (int i = 0; i < 10; i++) { e[i] = expf(logits[i] - m); sum += e[i]; }
        float inv = 1.0f / sum;
#pragma unroll
        for (int i = 0; i < 10; i++) out[g * 10 + i] = e[i] * inv;
    }
}

// ---------------- launch ----------------------------------------------------
extern "C" void kernel_launch(void* const* d_in, const int* in_sizes, int n_in,
                              void* d_out, int out_size) {
    const float* node_attr = (const float*)d_in[0];
    const float* Wc        = (const float*)d_in[1];
    const float* bc        = (const float*)d_in[2];
    const float* Wf1       = (const float*)d_in[3];
    const float* bf1       = (const float*)d_in[4];
    const float* Wf2       = (const float*)d_in[5];
    const float* bf2       = (const float*)d_in[6];
    const int*   src       = (const int*)d_in[7];
    const int*   dst       = (const int*)d_in[8];
    const int*   batching  = (const int*)d_in[9];
    float* out = (float*)d_out;

    float *bufA, *bufB;
    cudaGetSymbolAddress((void**)&bufA, g_bufA);
    cudaGetSymbolAddress((void**)&bufB, g_bufB);

    cudaFuncSetAttribute((const void*)gemm_bias_relu,
                         cudaFuncAttributeMaxDynamicSharedMemorySize, 131072);

    // build CSR-by-dst (deterministic work each call)
    init_kernel<<<(N_GRAPHS * F + 255) / 256 + 390, 256>>>();   // covers max(100000,131072)
    hist_kernel<<<(N_EDGES + 255) / 256, 256>>>(dst);
    scan_kernel<<<1, 1024>>>();
    scatter_kernel<<<(N_EDGES + 255) / 256, 256>>>(src, dst);

    // three conv layers
    const int agg_blocks  = (N_NODES * 32 + 255) / 256;
    const int gemm_blocks = (N_NODES + 127) / 128;

    const float* xin = node_attr;
    float* xout = bufA;
    for (int L = 0; L < 3; L++) {
        agg_kernel<<<agg_blocks, 256>>>(xin);
        gemm_bias_relu<<<gemm_blocks, 256, 131072>>>(Wc + (size_t)L * F * F,
                                                     bc + (size_t)L * F, xout, N_NODES);
        xin = xout;
        xout = (L == 0) ? bufB : bufA;
    }
    // after L0->bufA, L1->bufB, L2->bufA : final features in bufA
    const float* xfinal = bufA;

    pool_kernel<<<(N_NODES * 32 + 255) / 256, 256>>>(xfinal, batching);
    head_kernel<<<N_GRAPHS, 128>>>(Wf1, bf1, Wf2, bf2, out);
}

// round 4
// speedup vs baseline: 1.4745x; 1.4745x over previous
#include <cuda_runtime.h>
#include <cuda_bf16.h>
#include <cstdint>
#include <math.h>

#define N_NODES  100000
#define N_EDGES  3200000
#define N_GRAPHS 1024
#define F        128

// ---------------- scratch (device globals; no allocation allowed) ----------
__device__ float g_bufA[(size_t)N_NODES * F];
__device__ float g_bufB[(size_t)N_NODES * F];
__device__ float g_agg [(size_t)N_NODES * F];
__device__ int   g_cnt[N_NODES];
__device__ int   g_rowstart[N_NODES + 1];
__device__ int   g_cursor[N_NODES];
__device__ int   g_ssrc[N_EDGES];
__device__ float g_pool[N_GRAPHS * F];
__device__ int   g_bsum[128];
// bf16 hi/lo images of W, stored as Bt[n][k] (n-major): [layer][hi/lo][128n x 128k]
__device__ __nv_bfloat16 g_Wimg[3][2][16384];

// ============================ PTX helpers ===================================
__device__ __forceinline__ uint32_t smem_u32(const void* p) {
    uint32_t a;
    asm("{ .reg .u64 t; cvta.to.shared.u64 t, %1; cvt.u32.u64 %0, t; }"
        : "=r"(a) : "l"(p));
    return a;
}

__device__ __forceinline__ void ldsm4(uint32_t* r, uint32_t p) {
    asm volatile("ldmatrix.sync.aligned.m8n8.x4.shared.b16 {%0,%1,%2,%3}, [%4];"
        : "=r"(r[0]), "=r"(r[1]), "=r"(r[2]), "=r"(r[3]) : "r"(p));
}

__device__ __forceinline__ void mma16816(float* d, const uint32_t* a, const uint32_t* b) {
    asm volatile(
        "mma.sync.aligned.m16n8k16.row.col.f32.bf16.bf16.f32 "
        "{%0,%1,%2,%3}, {%4,%5,%6,%7}, {%8,%9}, {%0,%1,%2,%3};"
        : "+f"(d[0]), "+f"(d[1]), "+f"(d[2]), "+f"(d[3])
        : "r"(a[0]), "r"(a[1]), "r"(a[2]), "r"(a[3]), "r"(b[0]), "r"(b[1]));
}

// ---------------- init: zero histogram + pool ------------------------------
__global__ void init_kernel() {
    int i = blockIdx.x * blockDim.x + threadIdx.x;
    if (i < N_NODES) g_cnt[i] = 0;
    if (i < N_GRAPHS * F) g_pool[i] = 0.0f;
}

// ---------------- histogram of dst ------------------------------------------
__global__ void hist_kernel(const int* __restrict__ dst) {
    int i = blockIdx.x * blockDim.x + threadIdx.x;
    if (i < N_EDGES) atomicAdd(&g_cnt[dst[i]], 1);
}

// ---------------- multi-block exclusive scan --------------------------------
__global__ void scan_blocks() {
    __shared__ int wsum[32];
    int tid = threadIdx.x, lane = tid & 31, wid = tid >> 5;
    int i = blockIdx.x * 1024 + tid;
    int v = (i < N_NODES) ? g_cnt[i] : 0;
    int val = v;
#pragma unroll
    for (int off = 1; off < 32; off <<= 1) {
        int n = __shfl_up_sync(0xffffffffu, val, off);
        if (lane >= off) val += n;
    }
    if (lane == 31) wsum[wid] = val;
    __syncthreads();
    if (wid == 0) {
        int w = wsum[lane];
        int wv = w;
#pragma unroll
        for (int off = 1; off < 32; off <<= 1) {
            int n = __shfl_up_sync(0xffffffffu, wv, off);
            if (lane >= off) wv += n;
        }
        wsum[lane] = wv - w;
    }
    __syncthreads();
    int excl = wsum[wid] + val - v;
    if (i < N_NODES) g_rowstart[i] = excl;
    if (tid == 1023) g_bsum[blockIdx.x] = excl + v;
}

__global__ void scan_bsums(int nblocks) {
    __shared__ int wsum[4];
    int tid = threadIdx.x, lane = tid & 31, wid = tid >> 5;  // 128 threads
    int v = (tid < nblocks) ? g_bsum[tid] : 0;
    int val = v;
#pragma unroll
    for (int off = 1; off < 32; off <<= 1) {
        int n = __shfl_up_sync(0xffffffffu, val, off);
        if (lane >= off) val += n;
    }
    if (lane == 31) wsum[wid] = val;
    __syncthreads();
    int base = 0;
    for (int w = 0; w < wid; w++) base += wsum[w];
    if (tid < nblocks) g_bsum[tid] = base + val - v;
}

__global__ void add_offsets() {
    int i = blockIdx.x * 1024 + threadIdx.x;
    if (i < N_NODES) {
        int rs = g_rowstart[i] + g_bsum[i >> 10];
        g_rowstart[i] = rs;
        g_cursor[i] = rs;
    }
    if (i == 0) g_rowstart[N_NODES] = N_EDGES;
}

// ---------------- scatter edges into CSR-by-dst -----------------------------
__global__ void scatter_kernel(const int* __restrict__ src, const int* __restrict__ dst) {
    int i = blockIdx.x * blockDim.x + threadIdx.x;
    if (i < N_EDGES) {
        int p = atomicAdd(&g_cursor[dst[i]], 1);
        g_ssrc[p] = src[i];
    }
}

// ---------------- aggregation: warp per node, atomic-free ------------------
__global__ void agg_kernel(const float* __restrict__ xin) {
    int warp = (blockIdx.x * blockDim.x + threadIdx.x) >> 5;
    int lane = threadIdx.x & 31;
    if (warp >= N_NODES) return;
    int beg = __ldg(&g_rowstart[warp]);
    int end = __ldg(&g_rowstart[warp + 1]);
    const float4* xv = (const float4*)xin;
    float4 acc = make_float4(0.f, 0.f, 0.f, 0.f);
    int e = beg;
    int n4 = beg + ((end - beg) & ~3);
    for (; e < n4; e += 4) {
        int s0 = __ldg(&g_ssrc[e + 0]);
        int s1 = __ldg(&g_ssrc[e + 1]);
        int s2 = __ldg(&g_ssrc[e + 2]);
        int s3 = __ldg(&g_ssrc[e + 3]);
        float4 v0 = __ldg(&xv[(size_t)s0 * 32 + lane]);
        float4 v1 = __ldg(&xv[(size_t)s1 * 32 + lane]);
        float4 v2 = __ldg(&xv[(size_t)s2 * 32 + lane]);
        float4 v3 = __ldg(&xv[(size_t)s3 * 32 + lane]);
        acc.x += v0.x; acc.y += v0.y; acc.z += v0.z; acc.w += v0.w;
        acc.x += v1.x; acc.y += v1.y; acc.z += v1.z; acc.w += v1.w;
        acc.x += v2.x; acc.y += v2.y; acc.z += v2.z; acc.w += v2.w;
        acc.x += v3.x; acc.y += v3.y; acc.z += v3.z; acc.w += v3.w;
    }
    for (; e < end; e++) {
        int s = __ldg(&g_ssrc[e]);
        float4 v = __ldg(&xv[(size_t)s * 32 + lane]);
        acc.x += v.x; acc.y += v.y; acc.z += v.z; acc.w += v.w;
    }
    ((float4*)g_agg)[(size_t)warp * 32 + lane] = acc;
}

// ---------------- W -> bf16 hi/lo images, Bt[n][k] layout -------------------
__global__ void prep_w(const float* __restrict__ Wc) {
    int i = blockIdx.x * blockDim.x + threadIdx.x;
    if (i >= 3 * 16384) return;
    int L = i >> 14;
    int e = i & 16383;
    int k = e >> 7;           // 0..127 (input dim)
    int n = e & 127;          // 0..127 (output dim)
    float w = Wc[(size_t)L * 16384 + k * 128 + n];
    __nv_bfloat16 hi = __float2bfloat16(w);
    float lof = w - __bfloat162float(hi);
    __nv_bfloat16 lo = __float2bfloat16(lof);
    g_Wimg[L][0][n * 128 + k] = hi;   // Bt[n][k]
    g_Wimg[L][1][n * 128 + k] = lo;
}

// ---------------- GEMM via mma.sync bf16x3: out = relu(g_agg @ W + b) -------
// CTA tile: 128 rows x 128 cols, K=128, 3 passes (AhBh, AhBl, AlBh).
// smem: Ah, Al, Bh, Bl each [128][136] bf16 (stride 272B -> ldmatrix conflict-free)
#define ASTRIDE 136
#define GEMM_SMEM (4 * 128 * ASTRIDE * 2)

__global__ __launch_bounds__(256, 1)
void gemm_mma(const __nv_bfloat16* __restrict__ wimg,   // [2][128][128] hi,lo Bt
              const float* __restrict__ bias,
              float* __restrict__ out, int M) {
    extern __shared__ __align__(16) char smem[];
    __nv_bfloat16* sAh = (__nv_bfloat16*)smem;
    __nv_bfloat16* sAl = sAh + 128 * ASTRIDE;
    __nv_bfloat16* sBh = sAl + 128 * ASTRIDE;
    __nv_bfloat16* sBl = sBh + 128 * ASTRIDE;
    int tid = threadIdx.x;
    int warp = tid >> 5;
    int lane = tid & 31;
    long row0 = (long)blockIdx.x * 128;

    // copy W images into padded smem (16B chunks = 8 bf16)
    {
        const uint4* wsrc = (const uint4*)wimg;   // hi: [0,2048), lo: [2048,4096)
#pragma unroll
        for (int i = tid; i < 2048; i += 256) {
            int n = i >> 4, kq = i & 15;
            *(uint4*)&sBh[n * ASTRIDE + kq * 8] = __ldg(&wsrc[i]);
            *(uint4*)&sBl[n * ASTRIDE + kq * 8] = __ldg(&wsrc[2048 + i]);
        }
    }

    // load A tile (fp32) from g_agg, split to bf16 hi/lo
    {
        const float4* av = (const float4*)g_agg;
#pragma unroll
        for (int it = 0; it < 8; it++) {
            int g = it * 256 + tid;          // 0..2047 groups of 8 elems
            int r = g >> 4;
            int kq = g & 15;
            float4 v0, v1;
            if (row0 + r < M) {
                v0 = __ldg(&av[(row0 + r) * 32 + kq * 2]);
                v1 = __ldg(&av[(row0 + r) * 32 + kq * 2 + 1]);
            } else {
                v0 = make_float4(0.f, 0.f, 0.f, 0.f);
                v1 = v0;
            }
            float f[8] = {v0.x, v0.y, v0.z, v0.w, v1.x, v1.y, v1.z, v1.w};
            __nv_bfloat16 h[8], l[8];
#pragma unroll
            for (int j = 0; j < 8; j++) {
                h[j] = __float2bfloat16(f[j]);
                l[j] = __float2bfloat16(f[j] - __bfloat162float(h[j]));
            }
            *(uint4*)&sAh[r * ASTRIDE + kq * 8] = *(uint4*)h;
            *(uint4*)&sAl[r * ASTRIDE + kq * 8] = *(uint4*)l;
        }
    }
    __syncthreads();

    // accumulators: 16 n-tiles (8 cols each) x 4 fp32
    float acc[16][4];
#pragma unroll
    for (int t = 0; t < 16; t++)
#pragma unroll
        for (int j = 0; j < 4; j++) acc[t][j] = 0.f;

    int m0 = warp * 16;
    // per-lane fragment address offsets (bytes)
    uint32_t a_off = (uint32_t)(((m0 + (lane & 15)) * ASTRIDE + ((lane >> 4) * 8)) * 2);
    uint32_t b_off = (uint32_t)((((lane & 7) + ((lane >> 4) << 3)) * ASTRIDE +
                                 (((lane >> 3) & 1) * 8)) * 2);

    const __nv_bfloat16* pa[3] = {sAh, sAh, sAl};
    const __nv_bfloat16* pb[3] = {sBh, sBl, sBh};

#pragma unroll
    for (int p = 0; p < 3; p++) {
        uint32_t abase = smem_u32(pa[p]) + a_off;
        uint32_t bbase = smem_u32(pb[p]) + b_off;
#pragma unroll
        for (int kt = 0; kt < 8; kt++) {
            uint32_t a[4];
            ldsm4(a, abase + kt * 32);               // k0 = kt*16 -> 32 bytes
#pragma unroll
            for (int np = 0; np < 8; np++) {
                uint32_t b[4];
                ldsm4(b, bbase + (uint32_t)(np * 16 * ASTRIDE * 2) + kt * 32);
                mma16816(acc[2 * np],     a, b);
                mma16816(acc[2 * np + 1], a, b + 2);
            }
        }
    }

    // epilogue: bias + relu, direct stores (float2 per tile-row)
    int r_lo = m0 + (lane >> 2);
    int cbase = 2 * (lane & 3);
#pragma unroll
    for (int t = 0; t < 16; t++) {
        int col = t * 8 + cbase;
        float b0 = __ldg(&bias[col]);
        float b1 = __ldg(&bias[col + 1]);
        if (row0 + r_lo < M) {
            float2 o;
            o.x = fmaxf(acc[t][0] + b0, 0.f);
            o.y = fmaxf(acc[t][1] + b1, 0.f);
            *(float2*)&out[(row0 + r_lo) * 128 + col] = o;
        }
        if (row0 + r_lo + 8 < M) {
            float2 o;
            o.x = fmaxf(acc[t][2] + b0, 0.f);
            o.y = fmaxf(acc[t][3] + b1, 0.f);
            *(float2*)&out[(row0 + r_lo + 8) * 128 + col] = o;
        }
    }
}

// ---------------- global sum pool: sorted-run segmented reduction -----------
__global__ void pool_kernel(const float* __restrict__ x, const int* __restrict__ batching) {
    int i = blockIdx.x * blockDim.x + threadIdx.x;
    int chunk = i >> 5;
    int q = i & 31;
    int n0 = chunk * 64;
    if (n0 >= N_NODES) return;
    int n1 = n0 + 64;
    if (n1 > N_NODES) n1 = N_NODES;
    const float4* xv = (const float4*)x;
    int curb = __ldg(&batching[n0]);
    float4 acc = make_float4(0.f, 0.f, 0.f, 0.f);
    for (int n = n0; n < n1; n++) {
        int b = __ldg(&batching[n]);
        if (b != curb) {
            float* dp = &g_pool[curb * F + q * 4];
            atomicAdd(dp + 0, acc.x); atomicAdd(dp + 1, acc.y);
            atomicAdd(dp + 2, acc.z); atomicAdd(dp + 3, acc.w);
            curb = b;
            acc = make_float4(0.f, 0.f, 0.f, 0.f);
        }
        float4 v = __ldg(&xv[(size_t)n * 32 + q]);
        acc.x += v.x; acc.y += v.y; acc.z += v.z; acc.w += v.w;
    }
    float* dp = &g_pool[curb * F + q * 4];
    atomicAdd(dp + 0, acc.x); atomicAdd(dp + 1, acc.y);
    atomicAdd(dp + 2, acc.z); atomicAdd(dp + 3, acc.w);
}

// ---------------- head: FC1 -> FC2 -> softmax --------------------------------
__global__ void head_kernel(const float* __restrict__ Wf1, const float* __restrict__ bf1,
                            const float* __restrict__ Wf2, const float* __restrict__ bf2,
                            float* __restrict__ out) {
    __shared__ float gs[128];
    __shared__ float hs[64];
    __shared__ float logits[10];
    int g = blockIdx.x, tid = threadIdx.x;
    gs[tid] = g_pool[g * F + tid];
    __syncthreads();
    if (tid < 64) {
        float s = __ldg(&bf1[tid]);
#pragma unroll 8
        for (int k = 0; k < 128; k++)
            s = fmaf(gs[k], __ldg(&Wf1[k * 64 + tid]), s);
        hs[tid] = s;
    }
    __syncthreads();
    if (tid < 10) {
        float s = __ldg(&bf2[tid]);
#pragma unroll 8
        for (int k = 0; k < 64; k++)
            s = fmaf(hs[k], __ldg(&Wf2[k * 10 + tid]), s);
        logits[tid] = s;
    }
    __syncthreads();
    if (tid == 0) {
        float m = logits[0];
#pragma unroll
        for (int i = 1; i < 10; i++) m = fmaxf(m, logits[i]);
        float e[10], sum = 0.f;
#pragma unroll
        for (int i = 0; i < 10; i++) { e[i] = expf(logits[i] - m); sum += e[i]; }
        float inv = 1.0f / sum;
#pragma unroll
        for (int i = 0; i < 10; i++) out[g * 10 + i] = e[i] * inv;
    }
}

// ---------------- launch ----------------------------------------------------
extern "C" void kernel_launch(void* const* d_in, const int* in_sizes, int n_in,
                              void* d_out, int out_size) {
    const float* node_attr = (const float*)d_in[0];
    const float* Wc        = (const float*)d_in[1];
    const float* bc        = (const float*)d_in[2];
    const float* Wf1       = (const float*)d_in[3];
    const float* bf1       = (const float*)d_in[4];
    const float* Wf2       = (const float*)d_in[5];
    const float* bf2       = (const float*)d_in[6];
    const int*   src       = (const int*)d_in[7];
    const int*   dst       = (const int*)d_in[8];
    const int*   batching  = (const int*)d_in[9];
    float* out = (float*)d_out;

    float *bufA, *bufB;
    cudaGetSymbolAddress((void**)&bufA, g_bufA);
    cudaGetSymbolAddress((void**)&bufB, g_bufB);
    __nv_bfloat16* wimg;
    cudaGetSymbolAddress((void**)&wimg, g_Wimg);

    cudaFuncSetAttribute((const void*)gemm_mma,
                         cudaFuncAttributeMaxDynamicSharedMemorySize, GEMM_SMEM);

    const int scan_nblk = (N_NODES + 1023) / 1024;   // 98

    // build CSR-by-dst + W images (deterministic work each call)
    init_kernel<<<(N_GRAPHS * F + 255) / 256, 256>>>();   // 131072 >= N_NODES
    prep_w<<<(3 * 16384 + 255) / 256, 256>>>(Wc);
    hist_kernel<<<(N_EDGES + 255) / 256, 256>>>(dst);
    scan_blocks<<<scan_nblk, 1024>>>();
    scan_bsums<<<1, 128>>>(scan_nblk);
    add_offsets<<<scan_nblk, 1024>>>();
    scatter_kernel<<<(N_EDGES + 255) / 256, 256>>>(src, dst);

    // three conv layers: agg -> mma GEMM(+bias+relu)
    const int agg_blocks  = (N_NODES * 32 + 255) / 256;
    const int gemm_blocks = (N_NODES + 127) / 128;

    const float* xin = node_attr;
    float* xout = bufA;
    for (int L = 0; L < 3; L++) {
        agg_kernel<<<agg_blocks, 256>>>(xin);
        gemm_mma<<<gemm_blocks, 256, GEMM_SMEM>>>(wimg + (size_t)L * 32768,
                                                  bc + (size_t)L * F, xout, N_NODES);
        xin = xout;
        xout = (L == 0) ? bufB : bufA;
    }
    const float* xfinal = bufA;   // L0->A, L1->B, L2->A

    pool_kernel<<<((N_NODES + 63) / 64 * 32 + 255) / 256, 256>>>(xfinal, batching);
    head_kernel<<<N_GRAPHS, 128>>>(Wf1, bf1, Wf2, bf2, out);
}